// round 5
// baseline (speedup 1.0000x reference)
#include <cuda_runtime.h>
#include <stdint.h>

// GLCMAttention round 5: shfl-free neighbor loads (L1-hot scalar LDGs),
// u8 per-thread histograms (64KB, 3 CTAs/SM), per-pixel grouped RMW,
// uint4+dp4a flush.
//
// hist layout (bank == owner-lane for every access):
//   byte addr = warp<<13 | (q*8+qs)<<7 | lane<<2 | angle
// counter id k = (q*8+qs)*4 + angle; thread t reduces counter t.

#define HIST_BYTES 65536
#define SMEM_TOTAL (HIST_BYTES + 256*4 + 16*4 + 16)

__device__ __forceinline__ unsigned q7(float v) { return (unsigned)(int)(v * 7.0f); }

// Thread t sums counter-id t across all 256 per-thread regions.
// uint4 loads: 8 regions x 8 x LDS.128, column staggered by (lane>>2).
__device__ __forceinline__ unsigned flush_hist(const unsigned char* hist,
                                               int t, int lane)
{
    unsigned acc = 0;
    const unsigned sel = 1u << ((t & 3) * 8);          // extract byte 'angle'
    const unsigned pairbase = (unsigned)(t >> 2) << 7; // pair row (128B)
    const unsigned kst = (unsigned)(lane >> 2) & 7u;   // stagger
    #pragma unroll
    for (int w = 0; w < 8; ++w) {
        unsigned base = ((unsigned)w << 13) | pairbase;
        #pragma unroll
        for (int k = 0; k < 8; ++k) {
            unsigned kk = ((unsigned)k + kst) & 7u;
            uint4 v = *(const uint4*)(hist + base + (kk << 4));
            acc = __dp4a(v.x, sel, acc);
            acc = __dp4a(v.y, sel, acc);
            acc = __dp4a(v.z, sel, acc);
            acc = __dp4a(v.w, sel, acc);
        }
    }
    return acc;
}

// One pixel's 4 angle-counter increments: 4 distinct bytes (angle offset),
// loads grouped before stores (same-address ordering preserved per pixel).
#define PIXEL(QV, A0, A1, A2, A3)                                            \
    {                                                                        \
        unsigned char* b = hb + ((QV) << 10);                                \
        unsigned char* pa = b + ((A0) << 7);                                 \
        unsigned char* pb = b + ((A1) << 7) + 1;                             \
        unsigned char* pc = b + ((A2) << 7) + 2;                             \
        unsigned char* pd = b + ((A3) << 7) + 3;                             \
        unsigned va = *pa, vb = *pb, vc = *pc, vd = *pd;                     \
        *pa = (unsigned char)(va + 1u);                                      \
        *pb = (unsigned char)(vb + 1u);                                      \
        *pc = (unsigned char)(vc + 1u);                                      \
        *pd = (unsigned char)(vd + 1u);                                      \
    }

// Process one row using next row nb (VALID => nb is in-image).
#define ROWBODY(NB, VALID)                                                   \
    {                                                                        \
        float4 nv = make_float4(0.f, 0.f, 0.f, 0.f);                         \
        float nlv = 0.f, nrv = 0.f;                                          \
        if (VALID) {                                                         \
            nv = *(const float4*)(NB);                                       \
            if (g != 0)  nlv = (NB)[-1];                                     \
            if (g != 63) nrv = (NB)[4];                                      \
        }                                                                    \
        unsigned n0 = q7(nv.x), n1 = q7(nv.y), n2 = q7(nv.z), n3 = q7(nv.w); \
        unsigned nl = q7(nlv), nr = q7(nrv);                                 \
        PIXEL(c0, cl, nl, n0, n1)                                            \
        PIXEL(c1, c0, n0, n1, n2)                                            \
        PIXEL(c2, c1, n1, n2, n3)                                            \
        PIXEL(c3, c2, n2, n3, nr)                                            \
        c0 = n0; c1 = n1; c2 = n2; c3 = n3; cl = nl;                         \
    }

__global__ void __launch_bounds__(256, 3)
glcm_attn_kernel(const float* __restrict__ x,
                 const float* __restrict__ W1,
                 const float* __restrict__ W2,
                 float* __restrict__ out)
{
    extern __shared__ unsigned char smem[];
    unsigned char* hist   = smem;
    unsigned*      totals = (unsigned*)(smem + HIST_BYTES);
    float*         feats  = (float*)(totals + 256);
    float*         scalep = feats + 16;

    const int t = threadIdx.x, lane = t & 31;
    const int bc = blockIdx.x;
    const float* xp = x   + (size_t)bc * 65536;
    float*       op = out + (size_t)bc * 65536;

    // ---- zero hist ----
    uint4* h4 = (uint4*)hist;
    #pragma unroll
    for (int i = 0; i < 16; ++i) h4[t + (i << 8)] = make_uint4(0u, 0u, 0u, 0u);
    __syncthreads();

    unsigned char* hb = hist + ((t >> 5) << 13) + (lane << 2);

    // thread -> (row strip, 4-col group)
    const int strip = t >> 6;            // rows [strip*64, strip*64+64)
    const int g     = t & 63;            // cols [g*4, g*4+4)
    const float* rowp = xp + strip * 64 * 256 + g * 4;

    // ---- prologue: quantize row 0 of strip ----
    {
        float4 cv0 = *(const float4*)rowp;
        float clv = (g != 0) ? rowp[-1] : 0.f;
        (void)clv;
        // fallthrough into registers below
        unsigned c0_ = q7(cv0.x);
        (void)c0_;
    }
    float4 cv = *(const float4*)rowp;
    float clv = (g != 0) ? rowp[-1] : 0.f;
    unsigned c0 = q7(cv.x), c1 = q7(cv.y), c2 = q7(cv.z), c3 = q7(cv.w);
    unsigned cl = q7(clv);
    unsigned acc = 0;

    // ---- phase 1: local rows 0..31 (max 128/counter) ----
    #pragma unroll 2
    for (int y = 0; y < 32; ++y) {
        const float* nb = rowp + 256;
        ROWBODY(nb, true)
        rowp = nb;
    }

    __syncthreads();
    acc += flush_hist(hist, t, lane);
    __syncthreads();
    #pragma unroll
    for (int i = 0; i < 16; ++i) h4[t + (i << 8)] = make_uint4(0u, 0u, 0u, 0u);
    __syncthreads();

    // ---- phase 2: local rows 32..62, then row 63 (pad unless strip<3) ----
    #pragma unroll 2
    for (int y = 32; y < 63; ++y) {
        const float* nb = rowp + 256;
        ROWBODY(nb, true)
        rowp = nb;
    }
    {
        const float* nb = rowp + 256;
        ROWBODY(nb, (strip < 3))
    }

    __syncthreads();
    acc += flush_hist(hist, t, lane);
    totals[t] = acc;
    __syncthreads();

    // ---- features: warp 0, lane l -> angle = l>>3, row i = l&7 ----
    if (t < 32) {
        int angle = t >> 3;
        int sub   = t & 7;
        const float inv = 1.0f / 65536.0f;
        float fi = (float)sub;
        float contrast = 0.f, homog = 0.f, energy = 0.f, corr = 0.f;
        #pragma unroll
        for (int j = 0; j < 8; ++j) {
            float p = (float)totals[(((sub << 3) + j) << 2) + angle] * inv;
            float d = fi - (float)j;
            contrast += d * d * p;
            homog    += p / (1.0f + fabsf(d));
            energy   += p * p;
            corr     += (fi - 3.5f) * ((float)j - 3.5f) * p;
        }
        #pragma unroll
        for (int off = 4; off; off >>= 1) {
            contrast += __shfl_down_sync(0xFFFFFFFFu, contrast, off);
            homog    += __shfl_down_sync(0xFFFFFFFFu, homog,    off);
            energy   += __shfl_down_sync(0xFFFFFFFFu, energy,   off);
            corr     += __shfl_down_sync(0xFFFFFFFFu, corr,     off);
        }
        if (sub == 0) {
            feats[angle * 4 + 0] = contrast;
            feats[angle * 4 + 1] = homog;
            feats[angle * 4 + 2] = energy;
            feats[angle * 4 + 3] = corr * (1.0f / 6.000001f);  // /(std^2+1e-6)
        }
    }
    __syncthreads();

    // ---- MLP diagonal ----
    if (t < 16) {
        float h = 0.f;
        #pragma unroll
        for (int f = 0; f < 16; ++f) h += feats[f] * W1[f * 16 + t];
        h = fmaxf(h, 0.0f);
        int c = bc & 63;
        float v = h * W2[t * 64 + c];
        #pragma unroll
        for (int off = 8; off; off >>= 1)
            v += __shfl_down_sync(0x0000FFFFu, v, off);
        if (t == 0) {
            float s = 1.0f / (1.0f + expf(-v));
            *scalep = 1.0f + s;
        }
    }
    __syncthreads();

    // ---- output: out = x * scale (x re-read, L2-hot) ----
    const float s = *scalep;
    #pragma unroll 4
    for (int k = 0; k < 64; ++k) {
        int i = t + (k << 8);
        float4 v = ((const float4*)xp)[i];
        v.x *= s; v.y *= s; v.z *= s; v.w *= s;
        ((float4*)op)[i] = v;
    }
}

extern "C" void kernel_launch(void* const* d_in, const int* in_sizes, int n_in,
                              void* d_out, int out_size)
{
    (void)in_sizes; (void)n_in; (void)out_size;
    const float* x  = (const float*)d_in[0];
    const float* W1 = (const float*)d_in[1];
    const float* W2 = (const float*)d_in[2];
    float* out = (float*)d_out;

    cudaFuncSetAttribute(glcm_attn_kernel,
                         cudaFuncAttributeMaxDynamicSharedMemorySize, SMEM_TOTAL);
    glcm_attn_kernel<<<512, 256, SMEM_TOTAL>>>(x, W1, W2, out);
}

// round 7
// speedup vs baseline: 1.4425x; 1.4425x over previous
#include <cuda_runtime.h>
#include <stdint.h>

// GLCMAttention round 7 (= round-6 design, grid fix for k2):
//  k1: GLCM hist (u8 per-thread regions, 64KB smem, 3 CTAs/SM) + feats + MLP
//      -> g_scale[bc].  8 px/thread/row, warp-aligned 32-row strips, shfl
//      neighbors, zero edge LDGs.
//  k2: out = x * g_scale[bc], grid 2048 (4 blocks/image), pure streaming.
//
// hist layout (bank == owner-lane for every access):
//   byte addr = warp<<13 | (q*8+qs)<<7 | lane<<2 | angle

#define HIST_BYTES 65536
#define SMEM_TOTAL (HIST_BYTES + 256*4 + 16*4 + 16)

__device__ float g_scale[512];

__device__ __forceinline__ unsigned q7(float v) { return (unsigned)(int)(v * 7.0f); }

// Thread t sums counter-id t across all 256 per-thread regions.
// uint4 loads, column staggered by (lane>>2): conflict-free.
__device__ __forceinline__ unsigned flush_hist(const unsigned char* hist,
                                               int t, int lane)
{
    unsigned acc = 0;
    const unsigned sel = 1u << ((t & 3) * 8);          // extract byte 'angle'
    const unsigned pairbase = (unsigned)(t >> 2) << 7; // pair row (128B)
    const unsigned kst = (unsigned)(lane >> 2) & 7u;
    #pragma unroll
    for (int w = 0; w < 8; ++w) {
        unsigned base = ((unsigned)w << 13) | pairbase;
        #pragma unroll
        for (int k = 0; k < 8; ++k) {
            unsigned kk = ((unsigned)k + kst) & 7u;
            uint4 v = *(const uint4*)(hist + base + (kk << 4));
            acc = __dp4a(v.x, sel, acc);
            acc = __dp4a(v.y, sel, acc);
            acc = __dp4a(v.z, sel, acc);
            acc = __dp4a(v.w, sel, acc);
        }
    }
    return acc;
}

// One pixel: 4 angle counters = 4 distinct bytes; loads grouped before stores.
#define PIXEL(QV, A0, A1, A2, A3)                                            \
    {                                                                        \
        unsigned char* b = hb + ((QV) << 10);                                \
        unsigned char* pa = b + ((A0) << 7);                                 \
        unsigned char* pb = b + ((A1) << 7) + 1;                             \
        unsigned char* pc = b + ((A2) << 7) + 2;                             \
        unsigned char* pd = b + ((A3) << 7) + 3;                             \
        unsigned va = *pa, vb = *pb, vc = *pc, vd = *pd;                     \
        *pa = (unsigned char)(va + 1u);                                      \
        *pb = (unsigned char)(vb + 1u);                                      \
        *pc = (unsigned char)(vc + 1u);                                      \
        *pd = (unsigned char)(vd + 1u);                                      \
    }

// Process current row (c0..c7, cl) against next row loaded from NB (VALID).
#define ROWBODY(NB, VALID)                                                   \
    {                                                                        \
        float4 va = make_float4(0.f,0.f,0.f,0.f);                            \
        float4 vb = make_float4(0.f,0.f,0.f,0.f);                            \
        if (VALID) {                                                         \
            va = *(const float4*)(NB);                                       \
            vb = *(const float4*)((NB) + 4);                                 \
        }                                                                    \
        unsigned n0=q7(va.x), n1=q7(va.y), n2=q7(va.z), n3=q7(va.w);         \
        unsigned n4=q7(vb.x), n5=q7(vb.y), n6=q7(vb.z), n7=q7(vb.w);         \
        unsigned nl = __shfl_up_sync(0xFFFFFFFFu, n7, 1);                    \
        if (lane == 0)  nl = 0u;                                             \
        unsigned nr = __shfl_down_sync(0xFFFFFFFFu, n0, 1);                  \
        if (lane == 31) nr = 0u;                                             \
        PIXEL(c0, cl, nl, n0, n1)                                            \
        PIXEL(c1, c0, n0, n1, n2)                                            \
        PIXEL(c2, c1, n1, n2, n3)                                            \
        PIXEL(c3, c2, n2, n3, n4)                                            \
        PIXEL(c4, c3, n3, n4, n5)                                            \
        PIXEL(c5, c4, n4, n5, n6)                                            \
        PIXEL(c6, c5, n5, n6, n7)                                            \
        PIXEL(c7, c6, n6, n7, nr)                                            \
        c0=n0; c1=n1; c2=n2; c3=n3; c4=n4; c5=n5; c6=n6; c7=n7; cl=nl;       \
    }

__global__ void __launch_bounds__(256, 3)
glcm_hist_kernel(const float* __restrict__ x,
                 const float* __restrict__ W1,
                 const float* __restrict__ W2)
{
    extern __shared__ unsigned char smem[];
    unsigned char* hist   = smem;
    unsigned*      totals = (unsigned*)(smem + HIST_BYTES);
    float*         feats  = (float*)(totals + 256);

    const int t = threadIdx.x, lane = t & 31, w = t >> 5;
    const int bc = blockIdx.x;
    const float* xp = x + (size_t)bc * 65536;

    // ---- zero hist ----
    uint4* h4 = (uint4*)hist;
    #pragma unroll
    for (int i = 0; i < 16; ++i) h4[t + (i << 8)] = make_uint4(0u,0u,0u,0u);
    __syncthreads();

    unsigned char* hb = hist + (w << 13) + (lane << 2);

    // warp w -> rows [w*32, w*32+32); lane -> cols [lane*8, lane*8+8)
    const float* rowp = xp + (w << 5) * 256 + (lane << 3);

    // prologue: quantize row 0 of strip
    float4 a0 = *(const float4*)rowp;
    float4 b0 = *(const float4*)(rowp + 4);
    unsigned c0=q7(a0.x), c1=q7(a0.y), c2=q7(a0.z), c3=q7(a0.w);
    unsigned c4=q7(b0.x), c5=q7(b0.y), c6=q7(b0.z), c7=q7(b0.w);
    unsigned cl = __shfl_up_sync(0xFFFFFFFFu, c7, 1);
    if (lane == 0) cl = 0u;
    unsigned acc = 0;

    // ---- phase 1: local rows 0..15 (max 8*16=128 per u8 counter) ----
    #pragma unroll 2
    for (int y = 0; y < 16; ++y) {
        const float* nb = rowp + 256;
        ROWBODY(nb, true)
        rowp = nb;
    }
    __syncthreads();
    acc += flush_hist(hist, t, lane);
    __syncthreads();
    #pragma unroll
    for (int i = 0; i < 16; ++i) h4[t + (i << 8)] = make_uint4(0u,0u,0u,0u);
    __syncthreads();

    // ---- phase 2: local rows 16..30, then 31 (pad only for warp 7) ----
    #pragma unroll 2
    for (int y = 16; y < 31; ++y) {
        const float* nb = rowp + 256;
        ROWBODY(nb, true)
        rowp = nb;
    }
    {
        const float* nb = rowp + 256;
        ROWBODY(nb, (w < 7))
    }
    __syncthreads();
    acc += flush_hist(hist, t, lane);
    totals[t] = acc;
    __syncthreads();

    // ---- features: warp 0, lane l -> angle = l>>3, row i = l&7 ----
    if (t < 32) {
        int angle = t >> 3;
        int sub   = t & 7;
        const float inv = 1.0f / 65536.0f;
        float fi = (float)sub;
        float contrast = 0.f, homog = 0.f, energy = 0.f, corr = 0.f;
        #pragma unroll
        for (int j = 0; j < 8; ++j) {
            float p = (float)totals[(((sub << 3) + j) << 2) + angle] * inv;
            float d = fi - (float)j;
            contrast += d * d * p;
            homog    += p / (1.0f + fabsf(d));
            energy   += p * p;
            corr     += (fi - 3.5f) * ((float)j - 3.5f) * p;
        }
        #pragma unroll
        for (int off = 4; off; off >>= 1) {
            contrast += __shfl_down_sync(0xFFFFFFFFu, contrast, off);
            homog    += __shfl_down_sync(0xFFFFFFFFu, homog,    off);
            energy   += __shfl_down_sync(0xFFFFFFFFu, energy,   off);
            corr     += __shfl_down_sync(0xFFFFFFFFu, corr,     off);
        }
        if (sub == 0) {
            feats[angle * 4 + 0] = contrast;
            feats[angle * 4 + 1] = homog;
            feats[angle * 4 + 2] = energy;
            feats[angle * 4 + 3] = corr * (1.0f / 6.000001f);  // /(std^2+1e-6)
        }
    }
    __syncthreads();

    // ---- MLP diagonal -> g_scale[bc] ----
    if (t < 16) {
        float h = 0.f;
        #pragma unroll
        for (int f = 0; f < 16; ++f) h += feats[f] * W1[f * 16 + t];
        h = fmaxf(h, 0.0f);
        int c = bc & 63;
        float v = h * W2[t * 64 + c];
        #pragma unroll
        for (int off = 8; off; off >>= 1)
            v += __shfl_down_sync(0x0000FFFFu, v, off);
        if (t == 0)
            g_scale[bc] = 1.0f + 1.0f / (1.0f + expf(-v));
    }
}

// k2: pure streaming scale. Block = 4096 float4 (quarter image),
// 512 images * 4 = 2048 blocks.
__global__ void __launch_bounds__(256)
glcm_scale_kernel(const float* __restrict__ x, float* __restrict__ out)
{
    const int blk = blockIdx.x;
    const float s = g_scale[blk >> 2];
    const float4* xs = (const float4*)x + (size_t)blk * 4096;
    float4*       os = (float4*)out     + (size_t)blk * 4096;
    const int t = threadIdx.x;
    #pragma unroll
    for (int k = 0; k < 16; ++k) {
        int i = t + (k << 8);
        float4 v = xs[i];
        v.x *= s; v.y *= s; v.z *= s; v.w *= s;
        os[i] = v;
    }
}

extern "C" void kernel_launch(void* const* d_in, const int* in_sizes, int n_in,
                              void* d_out, int out_size)
{
    (void)in_sizes; (void)n_in; (void)out_size;
    const float* x  = (const float*)d_in[0];
    const float* W1 = (const float*)d_in[1];
    const float* W2 = (const float*)d_in[2];
    float* out = (float*)d_out;

    cudaFuncSetAttribute(glcm_hist_kernel,
                         cudaFuncAttributeMaxDynamicSharedMemorySize, SMEM_TOTAL);
    glcm_hist_kernel<<<512, 256, SMEM_TOTAL>>>(x, W1, W2);
    glcm_scale_kernel<<<2048, 256>>>(x, out);
}

// round 8
// speedup vs baseline: 1.5322x; 1.0622x over previous
#include <cuda_runtime.h>
#include <stdint.h>

// GLCMAttention round 8: k1 software-pipelined (prefetch depth 2 rows),
// otherwise identical to round-7 champion.
//  k1: GLCM hist (u8 per-thread regions, 64KB smem, 3 CTAs/SM) + feats + MLP
//      -> g_scale[bc].  Warp w owns rows [w*32,w*32+32), lane owns 8 cols.
//  k2: out = x * g_scale[bc], grid 2048, pure streaming (72% DRAM measured).
//
// hist layout (bank == owner-lane for every access):
//   byte addr = warp<<13 | (q*8+qs)<<7 | lane<<2 | angle

#define HIST_BYTES 65536
#define SMEM_TOTAL (HIST_BYTES + 256*4 + 16*4 + 16)

__device__ float g_scale[512];

__device__ __forceinline__ unsigned q7(float v) { return (unsigned)(int)(v * 7.0f); }

// Thread t sums counter-id t across all 256 per-thread regions.
__device__ __forceinline__ unsigned flush_hist(const unsigned char* hist,
                                               int t, int lane)
{
    unsigned acc = 0;
    const unsigned sel = 1u << ((t & 3) * 8);          // extract byte 'angle'
    const unsigned pairbase = (unsigned)(t >> 2) << 7; // pair row (128B)
    const unsigned kst = (unsigned)(lane >> 2) & 7u;
    #pragma unroll
    for (int w = 0; w < 8; ++w) {
        unsigned base = ((unsigned)w << 13) | pairbase;
        #pragma unroll
        for (int k = 0; k < 8; ++k) {
            unsigned kk = ((unsigned)k + kst) & 7u;
            uint4 v = *(const uint4*)(hist + base + (kk << 4));
            acc = __dp4a(v.x, sel, acc);
            acc = __dp4a(v.y, sel, acc);
            acc = __dp4a(v.z, sel, acc);
            acc = __dp4a(v.w, sel, acc);
        }
    }
    return acc;
}

// One pixel: 4 angle counters = 4 distinct bytes; loads grouped before stores.
#define PIXEL(QV, A0, A1, A2, A3)                                            \
    {                                                                        \
        unsigned char* b = hb + ((QV) << 10);                                \
        unsigned char* pa = b + ((A0) << 7);                                 \
        unsigned char* pb = b + ((A1) << 7) + 1;                             \
        unsigned char* pc = b + ((A2) << 7) + 2;                             \
        unsigned char* pd = b + ((A3) << 7) + 3;                             \
        unsigned va = *pa, vb = *pb, vc = *pc, vd = *pd;                     \
        *pa = (unsigned char)(va + 1u);                                      \
        *pb = (unsigned char)(vb + 1u);                                      \
        *pc = (unsigned char)(vc + 1u);                                      \
        *pd = (unsigned char)(vd + 1u);                                      \
    }

// Load strip-local row R (8 floats for this lane) or zeros if out of image.
#define LOADROW(D0,D1,D2,D3,D4,D5,D6,D7,R)                                   \
    {                                                                        \
        float4 aa = make_float4(0.f,0.f,0.f,0.f);                            \
        float4 bb = make_float4(0.f,0.f,0.f,0.f);                            \
        if (((R) <= 32) && ((grow + (R)) < 256)) {                           \
            const float4* p = (const float4*)(rowbase + (size_t)(R) * 256);  \
            aa = p[0]; bb = p[1];                                            \
        }                                                                    \
        D0=aa.x; D1=aa.y; D2=aa.z; D3=aa.w;                                  \
        D4=bb.x; D5=bb.y; D6=bb.z; D7=bb.w;                                  \
    }

// Quantize a row + its warp-edge shfls.
#define QUANTROW(S0,S1,S2,S3,S4,S5,S6,S7)                                    \
    t0=q7(S0); t1=q7(S1); t2=q7(S2); t3=q7(S3);                              \
    t4=q7(S4); t5=q7(S5); t6=q7(S6); t7=q7(S7);                              \
    Lt = __shfl_up_sync(0xFFFFFFFFu, t7, 1);   if (lane == 0)  Lt = 0u;      \
    Rt = __shfl_down_sync(0xFFFFFFFFu, t0, 1); if (lane == 31) Rt = 0u;

// Pipeline step: quantize row Y+2 (from S regs), prefetch row Y+4 (into S
// regs), RMW row Y (qc vs qn), rotate.
#define STEP(Y,S0,S1,S2,S3,S4,S5,S6,S7)                                      \
    {                                                                        \
        unsigned t0,t1,t2,t3,t4,t5,t6,t7, Lt, Rt;                            \
        QUANTROW(S0,S1,S2,S3,S4,S5,S6,S7)                                    \
        LOADROW(S0,S1,S2,S3,S4,S5,S6,S7,(Y)+4)                               \
        PIXEL(qc0, Lc,  Ln,  qn0, qn1)                                       \
        PIXEL(qc1, qc0, qn0, qn1, qn2)                                       \
        PIXEL(qc2, qc1, qn1, qn2, qn3)                                       \
        PIXEL(qc3, qc2, qn2, qn3, qn4)                                       \
        PIXEL(qc4, qc3, qn3, qn4, qn5)                                       \
        PIXEL(qc5, qc4, qn4, qn5, qn6)                                       \
        PIXEL(qc6, qc5, qn5, qn6, qn7)                                       \
        PIXEL(qc7, qc6, qn6, qn7, Rn)                                        \
        qc0=qn0; qc1=qn1; qc2=qn2; qc3=qn3;                                  \
        qc4=qn4; qc5=qn5; qc6=qn6; qc7=qn7; Lc=Ln;                           \
        qn0=t0; qn1=t1; qn2=t2; qn3=t3;                                      \
        qn4=t4; qn5=t5; qn6=t6; qn7=t7; Ln=Lt; Rn=Rt;                        \
    }

__global__ void __launch_bounds__(256, 3)
glcm_hist_kernel(const float* __restrict__ x,
                 const float* __restrict__ W1,
                 const float* __restrict__ W2)
{
    extern __shared__ unsigned char smem[];
    unsigned char* hist   = smem;
    unsigned*      totals = (unsigned*)(smem + HIST_BYTES);
    float*         feats  = (float*)(totals + 256);

    const int t = threadIdx.x, lane = t & 31, w = t >> 5;
    const int bc = blockIdx.x;
    const float* xp = x + (size_t)bc * 65536;

    // ---- zero hist ----
    uint4* h4 = (uint4*)hist;
    #pragma unroll
    for (int i = 0; i < 16; ++i) h4[t + (i << 8)] = make_uint4(0u,0u,0u,0u);
    __syncthreads();

    unsigned char* hb = hist + (w << 13) + (lane << 2);

    const int grow = w << 5;                       // strip's global row 0
    const float* rowbase = xp + grow * 256 + (lane << 3);

    // ---- prologue: rows 0,1 quantized; rows 2,3 prefetched ----
    unsigned qc0,qc1,qc2,qc3,qc4,qc5,qc6,qc7, Lc;
    unsigned qn0,qn1,qn2,qn3,qn4,qn5,qn6,qn7, Ln, Rn;
    float fa0,fa1,fa2,fa3,fa4,fa5,fa6,fa7;
    float fb0,fb1,fb2,fb3,fb4,fb5,fb6,fb7;
    {
        unsigned t0,t1,t2,t3,t4,t5,t6,t7, Lt, Rt;
        LOADROW(fa0,fa1,fa2,fa3,fa4,fa5,fa6,fa7, 0)
        QUANTROW(fa0,fa1,fa2,fa3,fa4,fa5,fa6,fa7)
        qc0=t0; qc1=t1; qc2=t2; qc3=t3; qc4=t4; qc5=t5; qc6=t6; qc7=t7;
        Lc = Lt; (void)Rt;
        LOADROW(fa0,fa1,fa2,fa3,fa4,fa5,fa6,fa7, 1)
        QUANTROW(fa0,fa1,fa2,fa3,fa4,fa5,fa6,fa7)
        qn0=t0; qn1=t1; qn2=t2; qn3=t3; qn4=t4; qn5=t5; qn6=t6; qn7=t7;
        Ln = Lt; Rn = Rt;
    }
    LOADROW(fa0,fa1,fa2,fa3,fa4,fa5,fa6,fa7, 2)
    LOADROW(fb0,fb1,fb2,fb3,fb4,fb5,fb6,fb7, 3)

    unsigned acc = 0;

    // ---- phase 1: rows 0..15 (max 128 per u8 counter) ----
    #pragma unroll 2
    for (int y = 0; y < 16; y += 2) {
        STEP(y,   fa0,fa1,fa2,fa3,fa4,fa5,fa6,fa7)
        STEP(y+1, fb0,fb1,fb2,fb3,fb4,fb5,fb6,fb7)
    }
    __syncthreads();
    acc += flush_hist(hist, t, lane);
    __syncthreads();
    #pragma unroll
    for (int i = 0; i < 16; ++i) h4[t + (i << 8)] = make_uint4(0u,0u,0u,0u);
    __syncthreads();

    // ---- phase 2: rows 16..31 ----
    #pragma unroll 2
    for (int y = 16; y < 32; y += 2) {
        STEP(y,   fa0,fa1,fa2,fa3,fa4,fa5,fa6,fa7)
        STEP(y+1, fb0,fb1,fb2,fb3,fb4,fb5,fb6,fb7)
    }
    __syncthreads();
    acc += flush_hist(hist, t, lane);
    totals[t] = acc;
    __syncthreads();

    // ---- features: warp 0, lane l -> angle = l>>3, row i = l&7 ----
    if (t < 32) {
        int angle = t >> 3;
        int sub   = t & 7;
        const float inv = 1.0f / 65536.0f;
        float fi = (float)sub;
        float contrast = 0.f, homog = 0.f, energy = 0.f, corr = 0.f;
        #pragma unroll
        for (int j = 0; j < 8; ++j) {
            float p = (float)totals[(((sub << 3) + j) << 2) + angle] * inv;
            float d = fi - (float)j;
            contrast += d * d * p;
            homog    += p / (1.0f + fabsf(d));
            energy   += p * p;
            corr     += (fi - 3.5f) * ((float)j - 3.5f) * p;
        }
        #pragma unroll
        for (int off = 4; off; off >>= 1) {
            contrast += __shfl_down_sync(0xFFFFFFFFu, contrast, off);
            homog    += __shfl_down_sync(0xFFFFFFFFu, homog,    off);
            energy   += __shfl_down_sync(0xFFFFFFFFu, energy,   off);
            corr     += __shfl_down_sync(0xFFFFFFFFu, corr,     off);
        }
        if (sub == 0) {
            feats[angle * 4 + 0] = contrast;
            feats[angle * 4 + 1] = homog;
            feats[angle * 4 + 2] = energy;
            feats[angle * 4 + 3] = corr * (1.0f / 6.000001f);  // /(std^2+1e-6)
        }
    }
    __syncthreads();

    // ---- MLP diagonal -> g_scale[bc] ----
    if (t < 16) {
        float h = 0.f;
        #pragma unroll
        for (int f = 0; f < 16; ++f) h += feats[f] * W1[f * 16 + t];
        h = fmaxf(h, 0.0f);
        int c = bc & 63;
        float v = h * W2[t * 64 + c];
        #pragma unroll
        for (int off = 8; off; off >>= 1)
            v += __shfl_down_sync(0x0000FFFFu, v, off);
        if (t == 0)
            g_scale[bc] = 1.0f + 1.0f / (1.0f + expf(-v));
    }
}

// k2: pure streaming scale. 4 blocks/image, 2048 blocks.
__global__ void __launch_bounds__(256)
glcm_scale_kernel(const float* __restrict__ x, float* __restrict__ out)
{
    const int blk = blockIdx.x;
    const float s = g_scale[blk >> 2];
    const float4* xs = (const float4*)x + (size_t)blk * 4096;
    float4*       os = (float4*)out     + (size_t)blk * 4096;
    const int t = threadIdx.x;
    #pragma unroll
    for (int k = 0; k < 16; ++k) {
        int i = t + (k << 8);
        float4 v = xs[i];
        v.x *= s; v.y *= s; v.z *= s; v.w *= s;
        os[i] = v;
    }
}

extern "C" void kernel_launch(void* const* d_in, const int* in_sizes, int n_in,
                              void* d_out, int out_size)
{
    (void)in_sizes; (void)n_in; (void)out_size;
    const float* x  = (const float*)d_in[0];
    const float* W1 = (const float*)d_in[1];
    const float* W2 = (const float*)d_in[2];
    float* out = (float*)d_out;

    cudaFuncSetAttribute(glcm_hist_kernel,
                         cudaFuncAttributeMaxDynamicSharedMemorySize, SMEM_TOTAL);
    glcm_hist_kernel<<<512, 256, SMEM_TOTAL>>>(x, W1, W2);
    glcm_scale_kernel<<<2048, 256>>>(x, out);
}